// round 3
// baseline (speedup 1.0000x reference)
#include <cuda_runtime.h>

#define BATCH 4096
#define SEQ   200
#define EMB   128
#define VOCAB 100000

__global__ __launch_bounds__(128)
void pool_linear_kernel(const int* __restrict__ x,
                        const float* __restrict__ emb,
                        const float* __restrict__ W,
                        const float* __restrict__ bias,
                        float* __restrict__ out)
{
    const int row  = blockIdx.x;
    const int tid  = threadIdx.x;
    const int warp = tid >> 5;
    const int lane = tid & 31;

    __shared__ int   sidx[SEQ];
    __shared__ float sacc[4][EMB];
    __shared__ float red[2][EMB];

    // Stage indices: 200 ints, 128 threads -> 2 coalesced passes.
    {
        const int* xr = x + row * SEQ;
        if (tid < SEQ)        sidx[tid]       = xr[tid];
        if (tid + 128 < SEQ)  sidx[tid + 128] = xr[tid + 128];
    }
    __syncthreads();

    float4 acc = make_float4(0.f, 0.f, 0.f, 0.f);
    float  cntf = 0.f;

    // Each warp handles tokens s = warp + 4*i ; 50 iterations, branchless gather.
    #pragma unroll 10
    for (int i = 0; i < SEQ / 4; i++) {
        int idx  = sidx[warp + 4 * i];       // broadcast from smem
        float m  = (idx >= 0) ? 1.f : 0.f;
        int   ci = (idx >= 0) ? idx : 0;     // padding -> row 0 (L1-resident)
        const float4* e = reinterpret_cast<const float4*>(emb + ci * EMB);
        float4 v = __ldg(&e[lane]);          // unconditional coalesced 512B load
        acc.x = fmaf(m, v.x, acc.x);
        acc.y = fmaf(m, v.y, acc.y);
        acc.z = fmaf(m, v.z, acc.z);
        acc.w = fmaf(m, v.w, acc.w);
        cntf += m;
    }

    // Cross-warp reduction of the 128-dim accumulator and the counts.
    __shared__ float scnt[4];
    reinterpret_cast<float4*>(sacc[warp])[lane] = acc;
    if (lane == 0) scnt[warp] = cntf;        // uniform across lanes in warp
    __syncthreads();

    const int d = tid;                       // dim owned by this thread
    float total = sacc[0][d] + sacc[1][d] + sacc[2][d] + sacc[3][d];
    float count = scnt[0] + scnt[1] + scnt[2] + scnt[3];
    float pooled = total * (1.0f / count);   // count >= 1 guaranteed

    // Tiny linear: out[row][k] = sum_d pooled[d]*W[k][d] + b[k]
    red[0][d] = pooled * W[d];
    red[1][d] = pooled * W[EMB + d];
    __syncthreads();

    if (warp < 2) {
        float v = red[warp][lane] + red[warp][lane + 32]
                + red[warp][lane + 64] + red[warp][lane + 96];
        #pragma unroll
        for (int off = 16; off > 0; off >>= 1)
            v += __shfl_down_sync(0xFFFFFFFFu, v, off);
        if (lane == 0)
            out[row * 2 + warp] = v + bias[warp];
    }
}

extern "C" void kernel_launch(void* const* d_in, const int* in_sizes, int n_in,
                              void* d_out, int out_size)
{
    const int* x     = (const int*)d_in[0];       // int32 [4096,200]
    const float* emb = (const float*)d_in[1];     // [100000,128]
    const float* W   = (const float*)d_in[2];     // [2,128]
    const float* b   = (const float*)d_in[3];     // [2]
    float* out       = (float*)d_out;             // [4096,2]

    pool_linear_kernel<<<BATCH, 128>>>(x, emb, W, b, out);
}

// round 5
// speedup vs baseline: 1.2301x; 1.2301x over previous
#include <cuda_runtime.h>

#define BATCH 4096
#define SEQ   200
#define EMB   128

__global__ __launch_bounds__(128)
void pool_linear_kernel(const int* __restrict__ x,
                        const float* __restrict__ emb,
                        const float* __restrict__ W,
                        const float* __restrict__ bias,
                        float* __restrict__ out)
{
    const int row  = blockIdx.x;
    const int tid  = threadIdx.x;
    const int warp = tid >> 5;
    const int lane = tid & 31;

    __shared__ __align__(16) float sacc[4][EMB];   // float4 access -> 16B aligned
    __shared__ __align__(16) float red[2][EMB];
    __shared__ int   sidx[SEQ];     // compacted valid indices
    __shared__ int   scount;

    if (tid == 0) scount = 0;
    __syncthreads();

    // Load + warp-ballot compaction of valid indices (order irrelevant for a sum).
    {
        const int* xr = x + row * SEQ;
        #pragma unroll
        for (int base = 0; base < SEQ; base += 128) {
            int s   = base + tid;
            int idx = (s < SEQ) ? xr[s] : -1;
            bool valid = (idx >= 0);
            unsigned m = __ballot_sync(0xFFFFFFFFu, valid);
            int nwarp  = __popc(m);
            int wbase;
            if (lane == 0) wbase = atomicAdd(&scount, nwarp);
            wbase = __shfl_sync(0xFFFFFFFFu, wbase, 0);
            if (valid) {
                int off = __popc(m & ((1u << lane) - 1u));
                sidx[wbase + off] = idx;
            }
        }
    }
    __syncthreads();

    const int nv = scount;           // >= 1 (column 0 always valid)

    float4 acc = make_float4(0.f, 0.f, 0.f, 0.f);

    // Unconditional gathers over exactly the valid tokens; warp w takes i = w, w+4, ...
    #pragma unroll 8
    for (int i = warp; i < nv; i += 4) {
        int idx = sidx[i];           // smem broadcast
        const float4* e = reinterpret_cast<const float4*>(emb + idx * EMB);
        float4 v = __ldg(&e[lane]);  // coalesced 512B row load (emb rows are 512B aligned)
        acc.x += v.x; acc.y += v.y; acc.z += v.z; acc.w += v.w;
    }

    // Cross-warp reduction of the 128-dim accumulator.
    reinterpret_cast<float4*>(sacc[warp])[lane] = acc;
    __syncthreads();

    const int d = tid;               // dim owned by this thread
    float total  = sacc[0][d] + sacc[1][d] + sacc[2][d] + sacc[3][d];
    float pooled = total * (1.0f / (float)nv);

    // Tiny linear: out[row][k] = sum_d pooled[d]*W[k][d] + b[k]
    red[0][d] = pooled * W[d];
    red[1][d] = pooled * W[EMB + d];
    __syncthreads();

    if (warp < 2) {
        float v = red[warp][lane] + red[warp][lane + 32]
                + red[warp][lane + 64] + red[warp][lane + 96];
        #pragma unroll
        for (int off = 16; off > 0; off >>= 1)
            v += __shfl_down_sync(0xFFFFFFFFu, v, off);
        if (lane == 0)
            out[row * 2 + warp] = v + bias[warp];
    }
}

extern "C" void kernel_launch(void* const* d_in, const int* in_sizes, int n_in,
                              void* d_out, int out_size)
{
    const int* x     = (const int*)d_in[0];       // int32 [4096,200]
    const float* emb = (const float*)d_in[1];     // [100000,128]
    const float* W   = (const float*)d_in[2];     // [2,128]
    const float* b   = (const float*)d_in[3];     // [2]
    float* out       = (float*)d_out;             // [4096,2]

    pool_linear_kernel<<<BATCH, 128>>>(x, emb, W, b, out);
}